// round 10
// baseline (speedup 1.0000x reference)
#include <cuda_runtime.h>

#define NT 100000
#define NC 100000
#define NE 1600000
#define NEH (NE / 2)
#define NP 200000
#define NPH (NP / 2)
#define HD 128

// ---- scratch (static __device__, zero at load; u kernels restore zeros) ----
__device__ float  g_dis_t[NT];
__device__ float  g_sum_t[NT];
__device__ float  g_deg_c[NC];
__device__ float4 g_gc4[NC];
__device__ float4 g_xd4[NC];
__device__ float4 g_u[NT + NC];
__device__ float  g_M[36];

__device__ __forceinline__ void red_add_v4(float4* addr, float a, float b, float c, float d) {
    asm volatile("red.global.add.v4.f32 [%0], {%1,%2,%3,%4};"
                 :: "l"(addr), "f"(a), "f"(b), "f"(c), "f"(d) : "memory");
}

// ================= truck =================
__global__ void __launch_bounds__(256, 8) k_deg_t(const int* __restrict__ eit) {
    int t = blockIdx.x * blockDim.x + threadIdx.x;
    int base = t * 4;
    if (base >= NE) return;
    int4 ct4 = __ldcs((const int4*)(eit + NE + base));
    atomicAdd(&g_dis_t[ct4.x], 1.0f);
    atomicAdd(&g_dis_t[ct4.y], 1.0f);
    atomicAdd(&g_dis_t[ct4.z], 1.0f);
    atomicAdd(&g_dis_t[ct4.w], 1.0f);
}

__global__ void __launch_bounds__(256) k_dis_t() {
    int t = blockIdx.x * blockDim.x + threadIdx.x;
    int i = t * 4;
    if (i >= NT) return;
    float4 dt = *(float4*)&g_dis_t[i];
    dt.x = rsqrtf(dt.x + 1.0f); dt.y = rsqrtf(dt.y + 1.0f);
    dt.z = rsqrtf(dt.z + 1.0f); dt.w = rsqrtf(dt.w + 1.0f);
    *(float4*)&g_dis_t[i] = dt;
}

// half-range truck aggregation: edges [e0, e0+NEH)
__global__ void __launch_bounds__(256, 6) k_agg_t(const int* __restrict__ eit, int e0) {
    int t = blockIdx.x * blockDim.x + threadIdx.x;
    int base = e0 + t * 4;
    if (t * 4 >= NEH) return;
    int4 rt4 = __ldcs((const int4*)(eit + base));
    int4 ct4 = __ldcs((const int4*)(eit + NE + base));
    int rt[4] = {rt4.x, rt4.y, rt4.z, rt4.w};
    int ct[4] = {ct4.x, ct4.y, ct4.z, ct4.w};
    float dtr[4];
    #pragma unroll
    for (int k = 0; k < 4; k++) dtr[k] = g_dis_t[rt[k]];
    #pragma unroll
    for (int k = 0; k < 4; k++) atomicAdd(&g_sum_t[ct[k]], dtr[k]);
}

__global__ void __launch_bounds__(256) k_u_t() {
    int n = blockIdx.x * blockDim.x + threadIdx.x;
    if (n >= NT) return;
    float d = g_dis_t[n];
    g_u[n] = make_float4(d * g_sum_t[n] + d * d, 1.f, 0.f, 0.f);
    g_dis_t[n] = 0.f;
    g_sum_t[n] = 0.f;
}

// ================= car =================
__global__ void __launch_bounds__(256, 8) k_deg_c(const int* __restrict__ eic,
                                                  const float* __restrict__ ew) {
    int t = blockIdx.x * blockDim.x + threadIdx.x;
    int base = t * 4;
    if (base >= NE) return;
    int4   cc4 = __ldcs((const int4*)(eic + NE + base));
    float4 w4  = __ldcs((const float4*)(ew + base));
    atomicAdd(&g_deg_c[cc4.x], w4.x);
    atomicAdd(&g_deg_c[cc4.y], w4.y);
    atomicAdd(&g_deg_c[cc4.z], w4.z);
    atomicAdd(&g_deg_c[cc4.w], w4.w);
}

__global__ void __launch_bounds__(256) k_dis_c(const float* __restrict__ xcar) {
    int t = blockIdx.x * blockDim.x + threadIdx.x;
    int i = t * 4;
    if (i >= NC) return;
    float4 dc = *(float4*)&g_deg_c[i];
    float4 x0 = __ldcs((const float4*)(xcar + 3 * i));
    float4 x1 = __ldcs((const float4*)(xcar + 3 * i + 4));
    float4 x2 = __ldcs((const float4*)(xcar + 3 * i + 8));
    float d0 = rsqrtf(dc.x + 1.0f), d1 = rsqrtf(dc.y + 1.0f);
    float d2 = rsqrtf(dc.z + 1.0f), d3 = rsqrtf(dc.w + 1.0f);
    g_xd4[i + 0] = make_float4(x0.x, x0.y, x0.z, d0);
    g_xd4[i + 1] = make_float4(x0.w, x1.x, x1.y, d1);
    g_xd4[i + 2] = make_float4(x1.z, x1.w, x2.x, d2);
    g_xd4[i + 3] = make_float4(x2.y, x2.z, x2.w, d3);
}

// half-range car aggregation: edges [e0, e0+NEH)
__global__ void __launch_bounds__(256, 6) k_agg_c(const int* __restrict__ eic,
                                                  const float* __restrict__ ew, int e0) {
    int t = blockIdx.x * blockDim.x + threadIdx.x;
    int base = e0 + t * 4;
    if (t * 4 >= NEH) return;
    int4   rc4 = __ldcs((const int4*)(eic + base));
    int4   cc4 = __ldcs((const int4*)(eic + NE + base));
    float4 w4  = __ldcs((const float4*)(ew + base));
    int rc[4] = {rc4.x, rc4.y, rc4.z, rc4.w};
    int cc[4] = {cc4.x, cc4.y, cc4.z, cc4.w};
    float w[4] = {w4.x, w4.y, w4.z, w4.w};
    float4 xd[4];
    #pragma unroll
    for (int k = 0; k < 4; k++) xd[k] = g_xd4[rc[k]];
    #pragma unroll
    for (int k = 0; k < 4; k++) {
        float nw = xd[k].w * w[k];
        red_add_v4(&g_gc4[cc[k]], nw * xd[k].x, nw * xd[k].y, nw * xd[k].z, 0.f);
    }
}

__global__ void __launch_bounds__(256) k_u_c() {
    int c = blockIdx.x * blockDim.x + threadIdx.x;
    if (c >= NC) return;
    float4 gc = g_gc4[c];
    float4 xd = g_xd4[c];
    float d  = xd.w;
    float dd = d * d;
    g_u[NT + c] = make_float4(d * gc.x + dd * xd.x,
                              d * gc.y + dd * xd.y,
                              d * gc.z + dd * xd.z,
                              1.f);
    g_gc4[c] = make_float4(0.f, 0.f, 0.f, 0.f);
    g_deg_c[c] = 0.f;
}

// ================= weights / scoring =================
__global__ void k_M(const float* __restrict__ Wt, const float* __restrict__ bt,
                    const float* __restrict__ Wc, const float* __restrict__ bc,
                    const float* __restrict__ wl) {
    __shared__ float B[6][HD];
    __shared__ float Bw[HD];
    int h = threadIdx.x;
    B[0][h] = Wt[h];
    B[1][h] = bt[h];
    B[2][h] = Wc[h];
    B[3][h] = Wc[HD + h];
    B[4][h] = Wc[2 * HD + h];
    B[5][h] = bc[h];
    Bw[h] = wl[h];
    __syncthreads();
    int warp = h >> 5, lane = h & 31;
    for (int pi = warp; pi < 36; pi += 4) {
        int i = pi / 6, j = pi % 6;
        float s = 0.f;
        #pragma unroll
        for (int t = lane; t < HD; t += 32)
            s += B[i][t] * B[j][t] * Bw[t];
        #pragma unroll
        for (int o = 16; o > 0; o >>= 1)
            s += __shfl_xor_sync(0xffffffff, s, o);
        if (lane == 0) g_M[pi] = s;
    }
}

// half-range pair scoring: pairs [p0, p0+NPH)
__global__ void __launch_bounds__(256) k_pair(const int* __restrict__ src,
                                              const int* __restrict__ dst,
                                              const float* __restrict__ bl,
                                              float* __restrict__ out, int p0) {
    __shared__ float M[36];
    if (threadIdx.x < 36) M[threadIdx.x] = g_M[threadIdx.x];
    __syncthreads();
    int t = blockIdx.x * blockDim.x + threadIdx.x;
    if (t * 2 >= NPH) return;
    int base = p0 + t * 2;
    int2 s2 = __ldcs((const int2*)(src + base));
    int2 d2 = __ldcs((const int2*)(dst + base));
    float blv = bl[0];
    int ss[2] = {s2.x, s2.y};
    int dd[2] = {d2.x, d2.y};
    float4 usv[2], udv[2];
    #pragma unroll
    for (int k = 0; k < 2; k++) { usv[k] = g_u[ss[k]]; udv[k] = g_u[dd[k]]; }
    float res[2];
    #pragma unroll
    for (int k = 0; k < 2; k++) {
        float us[6] = {0.f, 0.f, 0.f, 0.f, 0.f, 0.f};
        float ud[6] = {0.f, 0.f, 0.f, 0.f, 0.f, 0.f};
        if (ss[k] < NT) { us[0] = usv[k].x; us[1] = usv[k].y; }
        else            { us[2] = usv[k].x; us[3] = usv[k].y; us[4] = usv[k].z; us[5] = usv[k].w; }
        if (dd[k] < NT) { ud[0] = udv[k].x; ud[1] = udv[k].y; }
        else            { ud[2] = udv[k].x; ud[3] = udv[k].y; ud[4] = udv[k].z; ud[5] = udv[k].w; }
        float acc = blv;
        #pragma unroll
        for (int i = 0; i < 6; i++) {
            float tt = 0.f;
            #pragma unroll
            for (int j = 0; j < 6; j++)
                tt += M[6 * i + j] * ud[j];
            acc += us[i] * tt;
        }
        res[k] = acc;
    }
    out[base] = res[0];
    out[base + 1] = res[1];
}

extern "C" void kernel_launch(void* const* d_in, const int* in_sizes, int n_in,
                              void* d_out, int out_size) {
    const float* xcar = (const float*)d_in[0];
    const int*   eit  = (const int*)d_in[1];
    const int*   eic  = (const int*)d_in[2];
    const float* ew   = (const float*)d_in[3];
    const int*   src  = (const int*)d_in[4];
    const int*   dst  = (const int*)d_in[5];
    int w0 = (in_sizes[6] == 1) ? 7 : 6;
    const float* Wt = (const float*)d_in[w0 + 0];
    const float* bt = (const float*)d_in[w0 + 1];
    const float* Wc = (const float*)d_in[w0 + 2];
    const float* bc = (const float*)d_in[w0 + 3];
    const float* wl = (const float*)d_in[w0 + 4];
    const float* bl = (const float*)d_in[w0 + 5];
    float* out = (float*)d_out;

    // one-time infra: side stream + cross-stream events
    static cudaStream_t sB = 0;
    static cudaEvent_t eFork = 0, eDisT = 0, eDisC = 0, eAggTlo = 0, eAggChi = 0,
                       eUt = 0, eUc = 0, eTail = 0;
    if (sB == 0) {
        cudaStreamCreateWithFlags(&sB, cudaStreamNonBlocking);
        cudaEventCreateWithFlags(&eFork,   cudaEventDisableTiming);
        cudaEventCreateWithFlags(&eDisT,   cudaEventDisableTiming);
        cudaEventCreateWithFlags(&eDisC,   cudaEventDisableTiming);
        cudaEventCreateWithFlags(&eAggTlo, cudaEventDisableTiming);
        cudaEventCreateWithFlags(&eAggChi, cudaEventDisableTiming);
        cudaEventCreateWithFlags(&eUt,     cudaEventDisableTiming);
        cudaEventCreateWithFlags(&eUc,     cudaEventDisableTiming);
        cudaEventCreateWithFlags(&eTail,   cudaEventDisableTiming);
    }

    const int TPB = 256;
    const int GE  = (NE  / 4 + TPB - 1) / TPB;  // full edge set
    const int GEH = (NEH / 4 + TPB - 1) / TPB;  // half edge set
    const int GPH = (NPH / 2 + TPB - 1) / TPB;  // half pair set

    // fork
    cudaEventRecord(eFork, 0);
    cudaStreamWaitEvent(sB, eFork, 0);

    // --- phase 1: degrees (full graphs, one per stream) ---
    k_M<<<1, HD>>>(Wt, bt, Wc, bc, wl);          // sA, cheap
    k_deg_t<<<GE, TPB>>>(eit);                   // sA
    k_deg_c<<<GE, TPB, 0, sB>>>(eic, ew);        // sB

    // --- phase 2: dis ---
    k_dis_t<<<(NT / 4 + TPB - 1) / TPB, TPB>>>();                  // sA
    cudaEventRecord(eDisT, 0);
    k_dis_c<<<(NC / 4 + TPB - 1) / TPB, TPB, 0, sB>>>(xcar);       // sB
    cudaEventRecord(eDisC, sB);

    // --- phase 3: aggregation, each graph split across both streams ---
    k_agg_t<<<GEH, TPB>>>(eit, 0);                                  // sA: truck lo
    cudaStreamWaitEvent(sB, eDisT, 0);
    k_agg_t<<<GEH, TPB, 0, sB>>>(eit, NEH);                         // sB: truck hi
    cudaEventRecord(eAggTlo, sB);
    cudaStreamWaitEvent(0, eDisC, 0);
    k_agg_c<<<GEH, TPB>>>(eic, ew, 0);                              // sA: car lo
    cudaEventRecord(eAggChi, 0);
    k_agg_c<<<GEH, TPB, 0, sB>>>(eic, ew, NEH);                     // sB: car hi

    // --- phase 4: u vectors ---
    cudaStreamWaitEvent(0, eAggTlo, 0);   // u_t needs truck-hi (sB)
    k_u_t<<<(NT + TPB - 1) / TPB, TPB>>>();                         // sA
    cudaEventRecord(eUt, 0);
    cudaStreamWaitEvent(sB, eAggChi, 0);  // u_c needs car-lo (sA)
    k_u_c<<<(NC + TPB - 1) / TPB, TPB, 0, sB>>>();                  // sB
    cudaEventRecord(eUc, sB);

    // --- phase 5: pair scoring split across streams ---
    cudaStreamWaitEvent(0, eUc, 0);
    k_pair<<<GPH, TPB>>>(src, dst, bl, out, 0);                     // sA: lo
    cudaStreamWaitEvent(sB, eUt, 0);
    k_pair<<<GPH, TPB, 0, sB>>>(src, dst, bl, out, NPH);            // sB: hi
    cudaEventRecord(eTail, sB);
    cudaStreamWaitEvent(0, eTail, 0);     // join so the graph's end tracks both
}

// round 11
// speedup vs baseline: 1.0944x; 1.0944x over previous
#include <cuda_runtime.h>

#define NT 100000
#define NC 100000
#define NE 1600000
#define NP 200000
#define HD 128

// ---- scratch (static __device__, zero at load; u kernels restore zeros) ----
__device__ float  g_dis_t[NT];     // raw truck degree (never converted in place)
__device__ float  g_sum_t[NT];     // unscaled truck sum
__device__ float4 g_gc4[NC];       // unscaled car sum
__device__ float4 g_xd4[NC];       // (x0,x1,x2, raw weighted degree)
__device__ float4 g_u[NT + NC];    // per-node compact coefficients
__device__ float  g_M[36];         // 6x6 quadratic-form matrix

__device__ __forceinline__ void red_add_v4(float4* addr, float a, float b, float c, float d) {
    asm volatile("red.global.add.v4.f32 [%0], {%1,%2,%3,%4};"
                 :: "l"(addr), "f"(a), "f"(b), "f"(c), "f"(d) : "memory");
}

// ================= truck chain (stream A) =================
__global__ void __launch_bounds__(256, 8) k_deg_t(const int* __restrict__ eit) {
    int t = blockIdx.x * blockDim.x + threadIdx.x;
    int base = t * 4;
    if (base >= NE) return;
    int4 ct4 = __ldcs((const int4*)(eit + NE + base));
    atomicAdd(&g_dis_t[ct4.x], 1.0f);
    atomicAdd(&g_dis_t[ct4.y], 1.0f);
    atomicAdd(&g_dis_t[ct4.z], 1.0f);
    atomicAdd(&g_dis_t[ct4.w], 1.0f);
}

// inline rsqrt of raw degree; no separate dis kernel
__global__ void __launch_bounds__(256, 6) k_agg_t(const int* __restrict__ eit) {
    int t = blockIdx.x * blockDim.x + threadIdx.x;
    int base = t * 4;
    if (base >= NE) return;
    int4 rt4 = __ldcs((const int4*)(eit + base));
    int4 ct4 = __ldcs((const int4*)(eit + NE + base));
    int rt[4] = {rt4.x, rt4.y, rt4.z, rt4.w};
    int ct[4] = {ct4.x, ct4.y, ct4.z, ct4.w};
    float dtr[4];
    #pragma unroll
    for (int k = 0; k < 4; k++) dtr[k] = g_dis_t[rt[k]];
    #pragma unroll
    for (int k = 0; k < 4; k++)
        atomicAdd(&g_sum_t[ct[k]], rsqrtf(dtr[k] + 1.0f));
}

__global__ void __launch_bounds__(256) k_u_t() {
    int n = blockIdx.x * blockDim.x + threadIdx.x;
    if (n >= NT) return;
    float d = rsqrtf(g_dis_t[n] + 1.0f);
    g_u[n] = make_float4(d * g_sum_t[n] + d * d, 1.f, 0.f, 0.f);
    g_dis_t[n] = 0.f;
    g_sum_t[n] = 0.f;
}

// ================= car chain (stream B) =================
// degree atomics go straight into xd4.w; first NC/4 threads also pack x into xyz
__global__ void __launch_bounds__(256, 8) k_deg_c(const int* __restrict__ eic,
                                                  const float* __restrict__ ew,
                                                  const float* __restrict__ xcar) {
    int t = blockIdx.x * blockDim.x + threadIdx.x;
    // pack xcar -> xd4.xyz (independent of atomics; disjoint 4B words)
    int i = t * 4;
    if (i < NC) {
        float4 x0 = __ldcs((const float4*)(xcar + 3 * i));
        float4 x1 = __ldcs((const float4*)(xcar + 3 * i + 4));
        float4 x2 = __ldcs((const float4*)(xcar + 3 * i + 8));
        float* p0 = (float*)&g_xd4[i + 0];
        float* p1 = (float*)&g_xd4[i + 1];
        float* p2 = (float*)&g_xd4[i + 2];
        float* p3 = (float*)&g_xd4[i + 3];
        p0[0] = x0.x; p0[1] = x0.y; p0[2] = x0.z;
        p1[0] = x0.w; p1[1] = x1.x; p1[2] = x1.y;
        p2[0] = x1.z; p2[1] = x1.w; p2[2] = x2.x;
        p3[0] = x2.y; p3[1] = x2.z; p3[2] = x2.w;
    }
    int base = t * 4;
    if (base >= NE) return;
    int4   cc4 = __ldcs((const int4*)(eic + NE + base));
    float4 w4  = __ldcs((const float4*)(ew + base));
    atomicAdd(&g_xd4[cc4.x].w, w4.x);
    atomicAdd(&g_xd4[cc4.y].w, w4.y);
    atomicAdd(&g_xd4[cc4.z].w, w4.z);
    atomicAdd(&g_xd4[cc4.w].w, w4.w);
}

// single gather per edge; inline rsqrt of raw weighted degree
__global__ void __launch_bounds__(256, 6) k_agg_c(const int* __restrict__ eic,
                                                  const float* __restrict__ ew) {
    int t = blockIdx.x * blockDim.x + threadIdx.x;
    int base = t * 4;
    if (base >= NE) return;
    int4   rc4 = __ldcs((const int4*)(eic + base));
    int4   cc4 = __ldcs((const int4*)(eic + NE + base));
    float4 w4  = __ldcs((const float4*)(ew + base));
    int rc[4] = {rc4.x, rc4.y, rc4.z, rc4.w};
    int cc[4] = {cc4.x, cc4.y, cc4.z, cc4.w};
    float w[4] = {w4.x, w4.y, w4.z, w4.w};
    float4 xd[4];
    #pragma unroll
    for (int k = 0; k < 4; k++) xd[k] = g_xd4[rc[k]];
    #pragma unroll
    for (int k = 0; k < 4; k++) {
        float nw = rsqrtf(xd[k].w + 1.0f) * w[k];
        red_add_v4(&g_gc4[cc[k]], nw * xd[k].x, nw * xd[k].y, nw * xd[k].z, 0.f);
    }
}

__global__ void __launch_bounds__(256) k_u_c() {
    int c = blockIdx.x * blockDim.x + threadIdx.x;
    if (c >= NC) return;
    float4 gc = g_gc4[c];
    float4 xd = g_xd4[c];
    float d  = rsqrtf(xd.w + 1.0f);
    float dd = d * d;
    g_u[NT + c] = make_float4(d * gc.x + dd * xd.x,
                              d * gc.y + dd * xd.y,
                              d * gc.z + dd * xd.z,
                              1.f);
    g_gc4[c] = make_float4(0.f, 0.f, 0.f, 0.f);
    ((float*)&g_xd4[c])[3] = 0.f;   // reset raw degree for next replay
}

// ================= weights / scoring =================
__global__ void k_M(const float* __restrict__ Wt, const float* __restrict__ bt,
                    const float* __restrict__ Wc, const float* __restrict__ bc,
                    const float* __restrict__ wl) {
    __shared__ float B[6][HD];
    __shared__ float Bw[HD];
    int h = threadIdx.x;
    B[0][h] = Wt[h];
    B[1][h] = bt[h];
    B[2][h] = Wc[h];
    B[3][h] = Wc[HD + h];
    B[4][h] = Wc[2 * HD + h];
    B[5][h] = bc[h];
    Bw[h] = wl[h];
    __syncthreads();
    int warp = h >> 5, lane = h & 31;
    for (int pi = warp; pi < 36; pi += 4) {
        int i = pi / 6, j = pi % 6;
        float s = 0.f;
        #pragma unroll
        for (int t = lane; t < HD; t += 32)
            s += B[i][t] * B[j][t] * Bw[t];
        #pragma unroll
        for (int o = 16; o > 0; o >>= 1)
            s += __shfl_xor_sync(0xffffffff, s, o);
        if (lane == 0) g_M[pi] = s;
    }
}

__global__ void __launch_bounds__(256) k_pair(const int* __restrict__ src,
                                              const int* __restrict__ dst,
                                              const float* __restrict__ bl,
                                              float* __restrict__ out) {
    __shared__ float M[36];
    if (threadIdx.x < 36) M[threadIdx.x] = g_M[threadIdx.x];
    __syncthreads();
    int t = blockIdx.x * blockDim.x + threadIdx.x;
    int base = t * 2;
    if (base >= NP) return;
    int2 s2 = __ldcs((const int2*)(src + base));
    int2 d2 = __ldcs((const int2*)(dst + base));
    float blv = bl[0];
    int ss[2] = {s2.x, s2.y};
    int dd[2] = {d2.x, d2.y};
    float4 usv[2], udv[2];
    #pragma unroll
    for (int k = 0; k < 2; k++) { usv[k] = g_u[ss[k]]; udv[k] = g_u[dd[k]]; }
    float res[2];
    #pragma unroll
    for (int k = 0; k < 2; k++) {
        float us[6] = {0.f, 0.f, 0.f, 0.f, 0.f, 0.f};
        float ud[6] = {0.f, 0.f, 0.f, 0.f, 0.f, 0.f};
        if (ss[k] < NT) { us[0] = usv[k].x; us[1] = usv[k].y; }
        else            { us[2] = usv[k].x; us[3] = usv[k].y; us[4] = usv[k].z; us[5] = usv[k].w; }
        if (dd[k] < NT) { ud[0] = udv[k].x; ud[1] = udv[k].y; }
        else            { ud[2] = udv[k].x; ud[3] = udv[k].y; ud[4] = udv[k].z; ud[5] = udv[k].w; }
        float acc = blv;
        #pragma unroll
        for (int i = 0; i < 6; i++) {
            float tt = 0.f;
            #pragma unroll
            for (int j = 0; j < 6; j++)
                tt += M[6 * i + j] * ud[j];
            acc += us[i] * tt;
        }
        res[k] = acc;
    }
    out[base] = res[0];
    out[base + 1] = res[1];
}

extern "C" void kernel_launch(void* const* d_in, const int* in_sizes, int n_in,
                              void* d_out, int out_size) {
    const float* xcar = (const float*)d_in[0];
    const int*   eit  = (const int*)d_in[1];
    const int*   eic  = (const int*)d_in[2];
    const float* ew   = (const float*)d_in[3];
    const int*   src  = (const int*)d_in[4];
    const int*   dst  = (const int*)d_in[5];
    int w0 = (in_sizes[6] == 1) ? 7 : 6;
    const float* Wt = (const float*)d_in[w0 + 0];
    const float* bt = (const float*)d_in[w0 + 1];
    const float* Wc = (const float*)d_in[w0 + 2];
    const float* bc = (const float*)d_in[w0 + 3];
    const float* wl = (const float*)d_in[w0 + 4];
    const float* bl = (const float*)d_in[w0 + 5];
    float* out = (float*)d_out;

    static cudaStream_t sB = 0;
    static cudaEvent_t eFork = 0, eUc = 0;
    if (sB == 0) {
        cudaStreamCreateWithFlags(&sB, cudaStreamNonBlocking);
        cudaEventCreateWithFlags(&eFork, cudaEventDisableTiming);
        cudaEventCreateWithFlags(&eUc,   cudaEventDisableTiming);
    }

    const int TPB = 256;
    const int GE = (NE / 4 + TPB - 1) / TPB;

    cudaEventRecord(eFork, 0);
    cudaStreamWaitEvent(sB, eFork, 0);

    // stream B: car chain (3 kernels)
    k_deg_c<<<GE, TPB, 0, sB>>>(eic, ew, xcar);
    k_agg_c<<<GE, TPB, 0, sB>>>(eic, ew);
    k_u_c<<<(NC + TPB - 1) / TPB, TPB, 0, sB>>>();
    cudaEventRecord(eUc, sB);

    // stream A (default): weights + truck chain + pair
    k_M<<<1, HD>>>(Wt, bt, Wc, bc, wl);
    k_deg_t<<<GE, TPB>>>(eit);
    k_agg_t<<<GE, TPB>>>(eit);
    k_u_t<<<(NT + TPB - 1) / TPB, TPB>>>();
    cudaStreamWaitEvent(0, eUc, 0);   // join: pair needs car u's
    k_pair<<<(NP / 2 + TPB - 1) / TPB, TPB>>>(src, dst, bl, out);
}

// round 12
// speedup vs baseline: 1.1000x; 1.0051x over previous
#include <cuda_runtime.h>

#define NT 100000
#define NC 100000
#define NE 1600000
#define NP 200000
#define HD 128

// ---- scratch (static __device__, zero at load; u kernels restore zeros) ----
__device__ float  g_dis_t[NT];     // raw truck degree
__device__ float  g_sum_t[NT];     // unscaled truck sum
__device__ float4 g_gc4[NC];       // unscaled car sum
__device__ float4 g_xd4[NC];       // (x0,x1,x2, raw weighted degree)
__device__ float4 g_u[NT + NC];    // per-node compact coefficients

__device__ __forceinline__ void red_add_v4(float4* addr, float a, float b, float c, float d) {
    asm volatile("red.global.add.v4.f32 [%0], {%1,%2,%3,%4};"
                 :: "l"(addr), "f"(a), "f"(b), "f"(c), "f"(d) : "memory");
}

// ================= truck chain (stream A) =================
__global__ void __launch_bounds__(256, 8) k_deg_t(const int* __restrict__ eit) {
    int t = blockIdx.x * blockDim.x + threadIdx.x;
    int base = t * 4;
    if (base >= NE) return;
    int4 ct4 = __ldcs((const int4*)(eit + NE + base));
    atomicAdd(&g_dis_t[ct4.x], 1.0f);
    atomicAdd(&g_dis_t[ct4.y], 1.0f);
    atomicAdd(&g_dis_t[ct4.z], 1.0f);
    atomicAdd(&g_dis_t[ct4.w], 1.0f);
}

__global__ void __launch_bounds__(256, 6) k_agg_t(const int* __restrict__ eit) {
    int t = blockIdx.x * blockDim.x + threadIdx.x;
    int base = t * 4;
    if (base >= NE) return;
    int4 rt4 = __ldcs((const int4*)(eit + base));
    int4 ct4 = __ldcs((const int4*)(eit + NE + base));
    int rt[4] = {rt4.x, rt4.y, rt4.z, rt4.w};
    int ct[4] = {ct4.x, ct4.y, ct4.z, ct4.w};
    float dtr[4];
    #pragma unroll
    for (int k = 0; k < 4; k++) dtr[k] = g_dis_t[rt[k]];
    #pragma unroll
    for (int k = 0; k < 4; k++)
        atomicAdd(&g_sum_t[ct[k]], rsqrtf(dtr[k] + 1.0f));
}

__global__ void __launch_bounds__(256) k_u_t() {
    int n = blockIdx.x * blockDim.x + threadIdx.x;
    if (n >= NT) return;
    float d = rsqrtf(g_dis_t[n] + 1.0f);
    g_u[n] = make_float4(d * g_sum_t[n] + d * d, 1.f, 0.f, 0.f);
    g_dis_t[n] = 0.f;
    g_sum_t[n] = 0.f;
}

// ================= car chain (stream B) =================
__global__ void __launch_bounds__(256, 8) k_deg_c(const int* __restrict__ eic,
                                                  const float* __restrict__ ew,
                                                  const float* __restrict__ xcar) {
    int t = blockIdx.x * blockDim.x + threadIdx.x;
    int i = t * 4;
    if (i < NC) {
        float4 x0 = __ldcs((const float4*)(xcar + 3 * i));
        float4 x1 = __ldcs((const float4*)(xcar + 3 * i + 4));
        float4 x2 = __ldcs((const float4*)(xcar + 3 * i + 8));
        float* p0 = (float*)&g_xd4[i + 0];
        float* p1 = (float*)&g_xd4[i + 1];
        float* p2 = (float*)&g_xd4[i + 2];
        float* p3 = (float*)&g_xd4[i + 3];
        p0[0] = x0.x; p0[1] = x0.y; p0[2] = x0.z;
        p1[0] = x0.w; p1[1] = x1.x; p1[2] = x1.y;
        p2[0] = x1.z; p2[1] = x1.w; p2[2] = x2.x;
        p3[0] = x2.y; p3[1] = x2.z; p3[2] = x2.w;
    }
    int base = t * 4;
    if (base >= NE) return;
    int4   cc4 = __ldcs((const int4*)(eic + NE + base));
    float4 w4  = __ldcs((const float4*)(ew + base));
    atomicAdd(&g_xd4[cc4.x].w, w4.x);
    atomicAdd(&g_xd4[cc4.y].w, w4.y);
    atomicAdd(&g_xd4[cc4.z].w, w4.z);
    atomicAdd(&g_xd4[cc4.w].w, w4.w);
}

__global__ void __launch_bounds__(256, 6) k_agg_c(const int* __restrict__ eic,
                                                  const float* __restrict__ ew) {
    int t = blockIdx.x * blockDim.x + threadIdx.x;
    int base = t * 4;
    if (base >= NE) return;
    int4   rc4 = __ldcs((const int4*)(eic + base));
    int4   cc4 = __ldcs((const int4*)(eic + NE + base));
    float4 w4  = __ldcs((const float4*)(ew + base));
    int rc[4] = {rc4.x, rc4.y, rc4.z, rc4.w};
    int cc[4] = {cc4.x, cc4.y, cc4.z, cc4.w};
    float w[4] = {w4.x, w4.y, w4.z, w4.w};
    float4 xd[4];
    #pragma unroll
    for (int k = 0; k < 4; k++) xd[k] = g_xd4[rc[k]];
    #pragma unroll
    for (int k = 0; k < 4; k++) {
        float nw = rsqrtf(xd[k].w + 1.0f) * w[k];
        red_add_v4(&g_gc4[cc[k]], nw * xd[k].x, nw * xd[k].y, nw * xd[k].z, 0.f);
    }
}

__global__ void __launch_bounds__(256) k_u_c() {
    int c = blockIdx.x * blockDim.x + threadIdx.x;
    if (c >= NC) return;
    float4 gc = g_gc4[c];
    float4 xd = g_xd4[c];
    float d  = rsqrtf(xd.w + 1.0f);
    float dd = d * d;
    g_u[NT + c] = make_float4(d * gc.x + dd * xd.x,
                              d * gc.y + dd * xd.y,
                              d * gc.z + dd * xd.z,
                              1.f);
    g_gc4[c] = make_float4(0.f, 0.f, 0.f, 0.f);
    ((float*)&g_xd4[c])[3] = 0.f;
}

// ================= pair scoring with in-block M compute =================
__global__ void __launch_bounds__(256) k_pair(const int* __restrict__ src,
                                              const int* __restrict__ dst,
                                              const float* __restrict__ Wt,
                                              const float* __restrict__ bt,
                                              const float* __restrict__ Wc,
                                              const float* __restrict__ bc,
                                              const float* __restrict__ wl,
                                              const float* __restrict__ bl,
                                              float* __restrict__ out) {
    __shared__ float B[6][HD];
    __shared__ float Bw[HD];
    __shared__ float M[36];
    {
        int h = threadIdx.x;
        if (h < HD) {
            B[0][h] = __ldg(Wt + h);
            B[1][h] = __ldg(bt + h);
            B[2][h] = __ldg(Wc + h);
            B[3][h] = __ldg(Wc + HD + h);
            B[4][h] = __ldg(Wc + 2 * HD + h);
            B[5][h] = __ldg(bc + h);
            Bw[h]   = __ldg(wl + h);
        }
        __syncthreads();
        int warp = threadIdx.x >> 5, lane = threadIdx.x & 31;
        for (int pi = warp; pi < 36; pi += 8) {
            int i = pi / 6, j = pi % 6;
            float s = 0.f;
            #pragma unroll
            for (int tt = lane; tt < HD; tt += 32)
                s += B[i][tt] * B[j][tt] * Bw[tt];
            #pragma unroll
            for (int o = 16; o > 0; o >>= 1)
                s += __shfl_xor_sync(0xffffffff, s, o);
            if (lane == 0) M[pi] = s;
        }
        __syncthreads();
    }

    int t = blockIdx.x * blockDim.x + threadIdx.x;
    int base = t * 2;
    if (base >= NP) return;
    int2 s2 = __ldcs((const int2*)(src + base));
    int2 d2 = __ldcs((const int2*)(dst + base));
    float blv = __ldg(bl);
    int ss[2] = {s2.x, s2.y};
    int dd[2] = {d2.x, d2.y};
    float4 usv[2], udv[2];
    #pragma unroll
    for (int k = 0; k < 2; k++) { usv[k] = g_u[ss[k]]; udv[k] = g_u[dd[k]]; }
    float res[2];
    #pragma unroll
    for (int k = 0; k < 2; k++) {
        float us[6] = {0.f, 0.f, 0.f, 0.f, 0.f, 0.f};
        float ud[6] = {0.f, 0.f, 0.f, 0.f, 0.f, 0.f};
        if (ss[k] < NT) { us[0] = usv[k].x; us[1] = usv[k].y; }
        else            { us[2] = usv[k].x; us[3] = usv[k].y; us[4] = usv[k].z; us[5] = usv[k].w; }
        if (dd[k] < NT) { ud[0] = udv[k].x; ud[1] = udv[k].y; }
        else            { ud[2] = udv[k].x; ud[3] = udv[k].y; ud[4] = udv[k].z; ud[5] = udv[k].w; }
        float acc = blv;
        #pragma unroll
        for (int i = 0; i < 6; i++) {
            float tt = 0.f;
            #pragma unroll
            for (int j = 0; j < 6; j++)
                tt += M[6 * i + j] * ud[j];
            acc += us[i] * tt;
        }
        res[k] = acc;
    }
    out[base] = res[0];
    out[base + 1] = res[1];
}

extern "C" void kernel_launch(void* const* d_in, const int* in_sizes, int n_in,
                              void* d_out, int out_size) {
    const float* xcar = (const float*)d_in[0];
    const int*   eit  = (const int*)d_in[1];
    const int*   eic  = (const int*)d_in[2];
    const float* ew   = (const float*)d_in[3];
    const int*   src  = (const int*)d_in[4];
    const int*   dst  = (const int*)d_in[5];
    int w0 = (in_sizes[6] == 1) ? 7 : 6;
    const float* Wt = (const float*)d_in[w0 + 0];
    const float* bt = (const float*)d_in[w0 + 1];
    const float* Wc = (const float*)d_in[w0 + 2];
    const float* bc = (const float*)d_in[w0 + 3];
    const float* wl = (const float*)d_in[w0 + 4];
    const float* bl = (const float*)d_in[w0 + 5];
    float* out = (float*)d_out;

    static cudaStream_t sB = 0;
    static cudaEvent_t eFork = 0, eUc = 0;
    if (sB == 0) {
        cudaStreamCreateWithFlags(&sB, cudaStreamNonBlocking);
        cudaEventCreateWithFlags(&eFork, cudaEventDisableTiming);
        cudaEventCreateWithFlags(&eUc,   cudaEventDisableTiming);
    }

    const int TPB = 256;
    const int GE = (NE / 4 + TPB - 1) / TPB;

    cudaEventRecord(eFork, 0);
    cudaStreamWaitEvent(sB, eFork, 0);

    // stream B: car chain
    k_deg_c<<<GE, TPB, 0, sB>>>(eic, ew, xcar);
    k_agg_c<<<GE, TPB, 0, sB>>>(eic, ew);
    k_u_c<<<(NC + TPB - 1) / TPB, TPB, 0, sB>>>();
    cudaEventRecord(eUc, sB);

    // stream A (default): truck chain + pair
    k_deg_t<<<GE, TPB>>>(eit);
    k_agg_t<<<GE, TPB>>>(eit);
    k_u_t<<<(NT + TPB - 1) / TPB, TPB>>>();
    cudaStreamWaitEvent(0, eUc, 0);
    k_pair<<<(NP / 2 + TPB - 1) / TPB, TPB>>>(src, dst, Wt, bt, Wc, bc, wl, bl, out);
}

// round 13
// speedup vs baseline: 1.1044x; 1.0040x over previous
#include <cuda_runtime.h>

#define NT 100000
#define NC 100000
#define NE 1600000
#define NP 200000
#define HD 128

// ---- scratch (static __device__, zero at load; u kernels restore zeros) ----
__device__ float  g_dis_t[NT];     // raw truck degree
__device__ float  g_sum_t[NT];     // unscaled truck sum
__device__ float4 g_gc4[NC];       // unscaled car sum
__device__ float4 g_xd4[NC];       // (x0,x1,x2, raw weighted degree)
__device__ float4 g_u[NT + NC];    // per-node compact coefficients

__device__ __forceinline__ void red_add_v4(float4* addr, float a, float b, float c, float d) {
    asm volatile("red.global.add.v4.f32 [%0], {%1,%2,%3,%4};"
                 :: "l"(addr), "f"(a), "f"(b), "f"(c), "f"(d) : "memory");
}

// ================= stream A: truck chain (+ xcar packing) =================
// 8 edges/thread; also packs xcar into g_xd4.xyz (disjoint from car-deg atomics on .w)
__global__ void __launch_bounds__(256, 8) k_deg_t(const int* __restrict__ eit,
                                                  const float* __restrict__ xcar) {
    int t = blockIdx.x * blockDim.x + threadIdx.x;
    int i = t * 4;
    if (i < NC) {
        float4 x0 = __ldcs((const float4*)(xcar + 3 * i));
        float4 x1 = __ldcs((const float4*)(xcar + 3 * i + 4));
        float4 x2 = __ldcs((const float4*)(xcar + 3 * i + 8));
        float* p0 = (float*)&g_xd4[i + 0];
        float* p1 = (float*)&g_xd4[i + 1];
        float* p2 = (float*)&g_xd4[i + 2];
        float* p3 = (float*)&g_xd4[i + 3];
        p0[0] = x0.x; p0[1] = x0.y; p0[2] = x0.z;
        p1[0] = x0.w; p1[1] = x1.x; p1[2] = x1.y;
        p2[0] = x1.z; p2[1] = x1.w; p2[2] = x2.x;
        p3[0] = x2.y; p3[1] = x2.z; p3[2] = x2.w;
    }
    int base = t * 8;
    if (base >= NE) return;
    int4 a = __ldcs((const int4*)(eit + NE + base));
    int4 b = __ldcs((const int4*)(eit + NE + base + 4));
    atomicAdd(&g_dis_t[a.x], 1.0f);
    atomicAdd(&g_dis_t[a.y], 1.0f);
    atomicAdd(&g_dis_t[a.z], 1.0f);
    atomicAdd(&g_dis_t[a.w], 1.0f);
    atomicAdd(&g_dis_t[b.x], 1.0f);
    atomicAdd(&g_dis_t[b.y], 1.0f);
    atomicAdd(&g_dis_t[b.z], 1.0f);
    atomicAdd(&g_dis_t[b.w], 1.0f);
}

__global__ void __launch_bounds__(256, 6) k_agg_t(const int* __restrict__ eit) {
    int t = blockIdx.x * blockDim.x + threadIdx.x;
    int base = t * 4;
    if (base >= NE) return;
    int4 rt4 = __ldcs((const int4*)(eit + base));
    int4 ct4 = __ldcs((const int4*)(eit + NE + base));
    int rt[4] = {rt4.x, rt4.y, rt4.z, rt4.w};
    int ct[4] = {ct4.x, ct4.y, ct4.z, ct4.w};
    float dtr[4];
    #pragma unroll
    for (int k = 0; k < 4; k++) dtr[k] = g_dis_t[rt[k]];
    #pragma unroll
    for (int k = 0; k < 4; k++)
        atomicAdd(&g_sum_t[ct[k]], rsqrtf(dtr[k] + 1.0f));
}

__global__ void __launch_bounds__(256) k_u_t() {
    int n = blockIdx.x * blockDim.x + threadIdx.x;
    if (n >= NT) return;
    float d = rsqrtf(g_dis_t[n] + 1.0f);
    g_u[n] = make_float4(d * g_sum_t[n] + d * d, 1.f, 0.f, 0.f);
    g_dis_t[n] = 0.f;
    g_sum_t[n] = 0.f;
}

// ================= stream B: car chain =================
// 8 edges/thread; degree atomics into xd4.w (xyz packed by k_deg_t on stream A)
__global__ void __launch_bounds__(256, 8) k_deg_c(const int* __restrict__ eic,
                                                  const float* __restrict__ ew) {
    int t = blockIdx.x * blockDim.x + threadIdx.x;
    int base = t * 8;
    if (base >= NE) return;
    int4   ca = __ldcs((const int4*)(eic + NE + base));
    int4   cb = __ldcs((const int4*)(eic + NE + base + 4));
    float4 wa = __ldcs((const float4*)(ew + base));
    float4 wb = __ldcs((const float4*)(ew + base + 4));
    atomicAdd(&g_xd4[ca.x].w, wa.x);
    atomicAdd(&g_xd4[ca.y].w, wa.y);
    atomicAdd(&g_xd4[ca.z].w, wa.z);
    atomicAdd(&g_xd4[ca.w].w, wa.w);
    atomicAdd(&g_xd4[cb.x].w, wb.x);
    atomicAdd(&g_xd4[cb.y].w, wb.y);
    atomicAdd(&g_xd4[cb.z].w, wb.z);
    atomicAdd(&g_xd4[cb.w].w, wb.w);
}

__global__ void __launch_bounds__(256, 6) k_agg_c(const int* __restrict__ eic,
                                                  const float* __restrict__ ew) {
    int t = blockIdx.x * blockDim.x + threadIdx.x;
    int base = t * 4;
    if (base >= NE) return;
    int4   rc4 = __ldcs((const int4*)(eic + base));
    int4   cc4 = __ldcs((const int4*)(eic + NE + base));
    float4 w4  = __ldcs((const float4*)(ew + base));
    int rc[4] = {rc4.x, rc4.y, rc4.z, rc4.w};
    int cc[4] = {cc4.x, cc4.y, cc4.z, cc4.w};
    float w[4] = {w4.x, w4.y, w4.z, w4.w};
    float4 xd[4];
    #pragma unroll
    for (int k = 0; k < 4; k++) xd[k] = g_xd4[rc[k]];
    #pragma unroll
    for (int k = 0; k < 4; k++) {
        float nw = rsqrtf(xd[k].w + 1.0f) * w[k];
        red_add_v4(&g_gc4[cc[k]], nw * xd[k].x, nw * xd[k].y, nw * xd[k].z, 0.f);
    }
}

__global__ void __launch_bounds__(256) k_u_c() {
    int c = blockIdx.x * blockDim.x + threadIdx.x;
    if (c >= NC) return;
    float4 gc = g_gc4[c];
    float4 xd = g_xd4[c];
    float d  = rsqrtf(xd.w + 1.0f);
    float dd = d * d;
    g_u[NT + c] = make_float4(d * gc.x + dd * xd.x,
                              d * gc.y + dd * xd.y,
                              d * gc.z + dd * xd.z,
                              1.f);
    g_gc4[c] = make_float4(0.f, 0.f, 0.f, 0.f);
    ((float*)&g_xd4[c])[3] = 0.f;
}

// ================= pair scoring with in-block M compute =================
__global__ void __launch_bounds__(256) k_pair(const int* __restrict__ src,
                                              const int* __restrict__ dst,
                                              const float* __restrict__ Wt,
                                              const float* __restrict__ bt,
                                              const float* __restrict__ Wc,
                                              const float* __restrict__ bc,
                                              const float* __restrict__ wl,
                                              const float* __restrict__ bl,
                                              float* __restrict__ out) {
    __shared__ float B[6][HD];
    __shared__ float Bw[HD];
    __shared__ float M[36];
    {
        int h = threadIdx.x;
        if (h < HD) {
            B[0][h] = __ldg(Wt + h);
            B[1][h] = __ldg(bt + h);
            B[2][h] = __ldg(Wc + h);
            B[3][h] = __ldg(Wc + HD + h);
            B[4][h] = __ldg(Wc + 2 * HD + h);
            B[5][h] = __ldg(bc + h);
            Bw[h]   = __ldg(wl + h);
        }
        __syncthreads();
        int warp = threadIdx.x >> 5, lane = threadIdx.x & 31;
        for (int pi = warp; pi < 36; pi += 8) {
            int i = pi / 6, j = pi % 6;
            float s = 0.f;
            #pragma unroll
            for (int tt = lane; tt < HD; tt += 32)
                s += B[i][tt] * B[j][tt] * Bw[tt];
            #pragma unroll
            for (int o = 16; o > 0; o >>= 1)
                s += __shfl_xor_sync(0xffffffff, s, o);
            if (lane == 0) M[pi] = s;
        }
        __syncthreads();
    }

    int t = blockIdx.x * blockDim.x + threadIdx.x;
    int base = t * 2;
    if (base >= NP) return;
    int2 s2 = __ldcs((const int2*)(src + base));
    int2 d2 = __ldcs((const int2*)(dst + base));
    float blv = __ldg(bl);
    int ss[2] = {s2.x, s2.y};
    int dd[2] = {d2.x, d2.y};
    float4 usv[2], udv[2];
    #pragma unroll
    for (int k = 0; k < 2; k++) { usv[k] = g_u[ss[k]]; udv[k] = g_u[dd[k]]; }
    float res[2];
    #pragma unroll
    for (int k = 0; k < 2; k++) {
        float us[6] = {0.f, 0.f, 0.f, 0.f, 0.f, 0.f};
        float ud[6] = {0.f, 0.f, 0.f, 0.f, 0.f, 0.f};
        if (ss[k] < NT) { us[0] = usv[k].x; us[1] = usv[k].y; }
        else            { us[2] = usv[k].x; us[3] = usv[k].y; us[4] = usv[k].z; us[5] = usv[k].w; }
        if (dd[k] < NT) { ud[0] = udv[k].x; ud[1] = udv[k].y; }
        else            { ud[2] = udv[k].x; ud[3] = udv[k].y; ud[4] = udv[k].z; ud[5] = udv[k].w; }
        float acc = blv;
        #pragma unroll
        for (int i = 0; i < 6; i++) {
            float tt = 0.f;
            #pragma unroll
            for (int j = 0; j < 6; j++)
                tt += M[6 * i + j] * ud[j];
            acc += us[i] * tt;
        }
        res[k] = acc;
    }
    out[base] = res[0];
    out[base + 1] = res[1];
}

extern "C" void kernel_launch(void* const* d_in, const int* in_sizes, int n_in,
                              void* d_out, int out_size) {
    const float* xcar = (const float*)d_in[0];
    const int*   eit  = (const int*)d_in[1];
    const int*   eic  = (const int*)d_in[2];
    const float* ew   = (const float*)d_in[3];
    const int*   src  = (const int*)d_in[4];
    const int*   dst  = (const int*)d_in[5];
    int w0 = (in_sizes[6] == 1) ? 7 : 6;
    const float* Wt = (const float*)d_in[w0 + 0];
    const float* bt = (const float*)d_in[w0 + 1];
    const float* Wc = (const float*)d_in[w0 + 2];
    const float* bc = (const float*)d_in[w0 + 3];
    const float* wl = (const float*)d_in[w0 + 4];
    const float* bl = (const float*)d_in[w0 + 5];
    float* out = (float*)d_out;

    static cudaStream_t sB = 0;
    static cudaEvent_t eFork = 0, eDegT = 0, eUc = 0;
    if (sB == 0) {
        cudaStreamCreateWithFlags(&sB, cudaStreamNonBlocking);
        cudaEventCreateWithFlags(&eFork, cudaEventDisableTiming);
        cudaEventCreateWithFlags(&eDegT, cudaEventDisableTiming);
        cudaEventCreateWithFlags(&eUc,   cudaEventDisableTiming);
    }

    const int TPB = 256;
    const int GE8 = (NE / 8 + TPB - 1) / TPB;
    const int GE4 = (NE / 4 + TPB - 1) / TPB;

    cudaEventRecord(eFork, 0);
    cudaStreamWaitEvent(sB, eFork, 0);

    // stream A: truck chain (deg_t also packs xcar into xd4.xyz)
    k_deg_t<<<GE8, TPB>>>(eit, xcar);
    cudaEventRecord(eDegT, 0);
    k_agg_t<<<GE4, TPB>>>(eit);
    k_u_t<<<(NT + TPB - 1) / TPB, TPB>>>();

    // stream B: car chain (agg_c needs xd4.xyz packed by deg_t)
    k_deg_c<<<GE8, TPB, 0, sB>>>(eic, ew);
    cudaStreamWaitEvent(sB, eDegT, 0);
    k_agg_c<<<GE4, TPB, 0, sB>>>(eic, ew);
    k_u_c<<<(NC + TPB - 1) / TPB, TPB, 0, sB>>>();
    cudaEventRecord(eUc, sB);

    // join + score on stream A
    cudaStreamWaitEvent(0, eUc, 0);
    k_pair<<<(NP / 2 + TPB - 1) / TPB, TPB>>>(src, dst, Wt, bt, Wc, bc, wl, bl, out);
}